// round 7
// baseline (speedup 1.0000x reference)
#include <cuda_runtime.h>
#include <math.h>
#include <stdint.h>

// NeRFAcc occupancy-grid sampler.
// Inputs: origins [N,3] f32, directions [N,3] f32, occs [128^3] f32, aabb [2,3] f32.
// Output (flat f32): positions [N,S,3] | t_starts [N,S] | t_ends [N,S] | ray_idx [N,S] | mask [N,S]

#define RESG 128
#define NSTEPS 320
#define STEPF 0.01f
// alpha = 1-exp(-occ*STEP) > 0.01  <=>  occ > -ln(0.99)/STEP = 1.00503358535...
#define OCC_THRE 1.0050335853f

// 128^3 bits = 256 KB. Static device scratch (no allocation).
__device__ uint32_t g_bitgrid[RESG * RESG * RESG / 32];

// ---- kernel 1: compress occs (8 MB) -> binary grid (256 KB) -------------
__global__ __launch_bounds__(256)
void build_bitgrid_kernel(const float* __restrict__ occs)
{
    int tid = blockIdx.x * blockDim.x + threadIdx.x;   // 0 .. 128^3-1, z fastest
    float v = __ldg(occs + tid);
    unsigned b = __ballot_sync(0xffffffffu, v > OCC_THRE);
    if ((threadIdx.x & 31) == 0)
        g_bitgrid[tid >> 5] = b;
}

// ---- kernel 2: sampler ---------------------------------------------------
__device__ __forceinline__ void stcs4(float* p, float a, float b, float c, float d) {
    float4 v = make_float4(a, b, c, d);
    __stcs(reinterpret_cast<float4*>(p), v);
}

__global__ __launch_bounds__(256, 8)
void nerfacc_sampler_kernel(const float* __restrict__ origins,
                            const float* __restrict__ dirs,
                            const float* __restrict__ aabb,
                            float* __restrict__ out,
                            int N)
{
    const int CHUNKS = NSTEPS / 4;                 // 80 chunks of 4 steps
    int tid = blockIdx.x * blockDim.x + threadIdx.x;
    int total = N * CHUNKS;
    if (tid >= total) return;

    int ray = tid / CHUNKS;
    int s0  = (tid - ray * CHUNKS) * 4;

    // ---- per-ray data ----
    float ox = __ldg(origins + 3 * ray + 0);
    float oy = __ldg(origins + 3 * ray + 1);
    float oz = __ldg(origins + 3 * ray + 2);
    float dx = __ldg(dirs + 3 * ray + 0);
    float dy = __ldg(dirs + 3 * ray + 1);
    float dz = __ldg(dirs + 3 * ray + 2);

    float a0x = __ldg(aabb + 0), a0y = __ldg(aabb + 1), a0z = __ldg(aabb + 2);
    float a1x = __ldg(aabb + 3), a1y = __ldg(aabb + 4), a1z = __ldg(aabb + 5);

    // ---- robust slab intersection (matches reference exactly) ----
    float sdx = (fabsf(dx) < 1e-10f) ? 1e-10f : dx;
    float sdy = (fabsf(dy) < 1e-10f) ? 1e-10f : dy;
    float sdz = (fabsf(dz) < 1e-10f) ? 1e-10f : dz;
    float ivx = 1.0f / sdx, ivy = 1.0f / sdy, ivz = 1.0f / sdz;

    float t0x = (a0x - ox) * ivx, t1x = (a1x - ox) * ivx;
    float t0y = (a0y - oy) * ivy, t1y = (a1y - oy) * ivy;
    float t0z = (a0z - oz) * ivz, t1z = (a1z - oz) * ivz;

    float tmin = fmaxf(fmaxf(fminf(t0x, t1x), fminf(t0y, t1y)), fminf(t0z, t1z));
    float tmax = fminf(fminf(fmaxf(t0x, t1x), fmaxf(t0y, t1y)), fmaxf(t0z, t1z));
    tmin = fmaxf(tmin, 0.0f);                      // NEAR = 0

    float invsx = 1.0f / (a1x - a0x);
    float invsy = 1.0f / (a1y - a0y);
    float invsz = 1.0f / (a1z - a0z);

    bool ray_ok = (tmax > tmin);

    // ---- positions + predicated bit-grid gathers ----
    float P[12];
    unsigned mbits = 0;

    #pragma unroll
    for (int j = 0; j < 4; j++) {
        float t_start = fmaf((float)(s0 + j), STEPF, tmin);
        float t_end   = t_start + STEPF;
        float t_mid   = 0.5f * (t_start + t_end);

        float x = fmaf(dx, t_mid, ox);
        float y = fmaf(dy, t_mid, oy);
        float z = fmaf(dz, t_mid, oz);
        P[j * 3 + 0] = x;
        P[j * 3 + 1] = y;
        P[j * 3 + 2] = z;

        float ux = (x - a0x) * invsx;
        float uy = (y - a0y) * invsy;
        float uz = (z - a0z) * invsz;

        bool inside = (ux >= 0.0f) & (ux < 1.0f)
                    & (uy >= 0.0f) & (uy < 1.0f)
                    & (uz >= 0.0f) & (uz < 1.0f);

        if (inside && (t_end <= tmax) && ray_ok) {
            // inside => u in [0,1) => indices in [0,127], no clamp needed
            unsigned ix = (unsigned)(int)(ux * (float)RESG);
            unsigned iy = (unsigned)(int)(uy * (float)RESG);
            unsigned iz = (unsigned)(int)(uz * (float)RESG);
            unsigned widx = (((ix << 7) | iy) << 2) | (iz >> 5);
            uint32_t w = g_bitgrid[widx];
            if ((w >> (iz & 31u)) & 1u)
                mbits |= (1u << j);
        }
    }

    float mf0 = (mbits & 1u) ? 1.0f : 0.0f;
    float mf1 = (mbits & 2u) ? 1.0f : 0.0f;
    float mf2 = (mbits & 4u) ? 1.0f : 0.0f;
    float mf3 = (mbits & 8u) ? 1.0f : 0.0f;

    // ---- streaming stores (32-bit offsets; total < 2^31 bytes) ----
    unsigned NS  = (unsigned)N * NSTEPS;
    unsigned lin = (unsigned)ray * NSTEPS + (unsigned)s0;

    {   // positions: 12 consecutive floats at lin*3 (48B-aligned)
        float* pb = out + (size_t)lin * 3u;
        stcs4(pb + 0, P[0] * mf0, P[1]  * mf0, P[2]  * mf0, P[3]  * mf1);
        stcs4(pb + 4, P[4] * mf1, P[5]  * mf1, P[6]  * mf2, P[7]  * mf2);
        stcs4(pb + 8, P[8] * mf2, P[9]  * mf3, P[10] * mf3, P[11] * mf3);
    }

    {
        float t0 = fmaf((float)(s0 + 0), STEPF, tmin);
        float t1 = fmaf((float)(s0 + 1), STEPF, tmin);
        float t2 = fmaf((float)(s0 + 2), STEPF, tmin);
        float t3 = fmaf((float)(s0 + 3), STEPF, tmin);
        stcs4(out + (size_t)NS * 3u + lin, t0 * mf0, t1 * mf1, t2 * mf2, t3 * mf3);
        stcs4(out + (size_t)NS * 4u + lin, (t0 + STEPF) * mf0, (t1 + STEPF) * mf1,
                                           (t2 + STEPF) * mf2, (t3 + STEPF) * mf3);
    }

    float rf = (float)ray;
    stcs4(out + (size_t)NS * 5u + lin,
          (mbits & 1u) ? rf : -1.0f,
          (mbits & 2u) ? rf : -1.0f,
          (mbits & 4u) ? rf : -1.0f,
          (mbits & 8u) ? rf : -1.0f);

    stcs4(out + (size_t)NS * 6u + lin, mf0, mf1, mf2, mf3);
}

extern "C" void kernel_launch(void* const* d_in, const int* in_sizes, int n_in,
                              void* d_out, int out_size)
{
    const float* origins = (const float*)d_in[0];
    const float* dirs    = (const float*)d_in[1];
    const float* occs    = (const float*)d_in[2];
    const float* aabb    = (const float*)d_in[3];
    float* out           = (float*)d_out;

    int N = in_sizes[0] / 3;

    // kernel 1: occs -> bit grid (2M cells / 256 threads)
    build_bitgrid_kernel<<<(RESG * RESG * RESG) / 256, 256>>>(occs);

    // kernel 2: sampler
    int total = N * (NSTEPS / 4);
    int block = 256;
    int grid = (total + block - 1) / block;
    nerfacc_sampler_kernel<<<grid, block>>>(origins, dirs, aabb, out, N);
}

// round 10
// speedup vs baseline: 1.0892x; 1.0892x over previous
#include <cuda_runtime.h>
#include <math.h>
#include <stdint.h>

// NeRFAcc occupancy-grid sampler.
// Inputs: origins [N,3] f32, directions [N,3] f32, occs [128^3] f32, aabb [2,3] f32.
// Output (flat f32): positions [N,S,3] | t_starts [N,S] | t_ends [N,S] | ray_idx [N,S] | mask [N,S]

#define RESG 128
#define NSTEPS 320
#define STEPF 0.01f
// alpha = 1-exp(-occ*STEP) > 0.01  <=>  occ > -ln(0.99)/STEP = 1.00503358535...
#define OCC_THRE 1.0050335853f

__device__ __forceinline__ void st4(float* p, float a, float b, float c, float d) {
    *reinterpret_cast<float4*>(p) = make_float4(a, b, c, d);
}

__global__ __launch_bounds__(256, 8)
void nerfacc_sampler_kernel(const float* __restrict__ origins,
                            const float* __restrict__ dirs,
                            const float* __restrict__ occs,
                            const float* __restrict__ aabb,
                            float* __restrict__ out,
                            int N)
{
    const int CHUNKS = NSTEPS / 4;                 // 80 chunks of 4 steps
    int tid = blockIdx.x * blockDim.x + threadIdx.x;
    int total = N * CHUNKS;
    if (tid >= total) return;

    int ray = tid / CHUNKS;
    int s0  = (tid - ray * CHUNKS) * 4;

    // ---- per-ray data ----
    float ox = __ldg(origins + 3 * ray + 0);
    float oy = __ldg(origins + 3 * ray + 1);
    float oz = __ldg(origins + 3 * ray + 2);
    float dx = __ldg(dirs + 3 * ray + 0);
    float dy = __ldg(dirs + 3 * ray + 1);
    float dz = __ldg(dirs + 3 * ray + 2);

    float a0x = __ldg(aabb + 0), a0y = __ldg(aabb + 1), a0z = __ldg(aabb + 2);
    float a1x = __ldg(aabb + 3), a1y = __ldg(aabb + 4), a1z = __ldg(aabb + 5);

    // ---- robust slab intersection (matches reference exactly) ----
    float sdx = (fabsf(dx) < 1e-10f) ? 1e-10f : dx;
    float sdy = (fabsf(dy) < 1e-10f) ? 1e-10f : dy;
    float sdz = (fabsf(dz) < 1e-10f) ? 1e-10f : dz;
    float ivx = 1.0f / sdx, ivy = 1.0f / sdy, ivz = 1.0f / sdz;

    float t0x = (a0x - ox) * ivx, t1x = (a1x - ox) * ivx;
    float t0y = (a0y - oy) * ivy, t1y = (a1y - oy) * ivy;
    float t0z = (a0z - oz) * ivz, t1z = (a1z - oz) * ivz;

    float tmin = fmaxf(fmaxf(fminf(t0x, t1x), fminf(t0y, t1y)), fminf(t0z, t1z));
    float tmax = fminf(fminf(fmaxf(t0x, t1x), fmaxf(t0y, t1y)), fmaxf(t0z, t1z));
    tmin = fmaxf(tmin, 0.0f);                      // NEAR = 0

    float invsx = 1.0f / (a1x - a0x);
    float invsy = 1.0f / (a1y - a0y);
    float invsz = 1.0f / (a1z - a0z);

    bool ray_ok = (tmax > tmin);

    // ---- positions + predicated gathers + threshold test (no expf) ----
    float P[12];
    unsigned mbits = 0;

    #pragma unroll
    for (int j = 0; j < 4; j++) {
        float t_start = fmaf((float)(s0 + j), STEPF, tmin);
        float t_end   = t_start + STEPF;
        float t_mid   = 0.5f * (t_start + t_end);

        float x = fmaf(dx, t_mid, ox);
        float y = fmaf(dy, t_mid, oy);
        float z = fmaf(dz, t_mid, oz);
        P[j * 3 + 0] = x;
        P[j * 3 + 1] = y;
        P[j * 3 + 2] = z;

        float ux = (x - a0x) * invsx;
        float uy = (y - a0y) * invsy;
        float uz = (z - a0z) * invsz;

        bool inside = (ux >= 0.0f) & (ux < 1.0f)
                    & (uy >= 0.0f) & (uy < 1.0f)
                    & (uz >= 0.0f) & (uz < 1.0f);

        if (inside && (t_end <= tmax) && ray_ok) {
            // inside => u in [0,1) => indices in [0,127], no clamp needed
            unsigned ix = (unsigned)(int)(ux * (float)RESG);
            unsigned iy = (unsigned)(int)(uy * (float)RESG);
            unsigned iz = (unsigned)(int)(uz * (float)RESG);
            float occ = __ldg(occs + (((ix << 7) | iy) << 7 | iz));
            if (occ > OCC_THRE)
                mbits |= (1u << j);
        }
    }

    float mf0 = (mbits & 1u) ? 1.0f : 0.0f;
    float mf1 = (mbits & 2u) ? 1.0f : 0.0f;
    float mf2 = (mbits & 4u) ? 1.0f : 0.0f;
    float mf3 = (mbits & 8u) ? 1.0f : 0.0f;

    // ---- coalesced float4 stores (default caching: let L2 hold dirty lines) ----
    unsigned NS  = (unsigned)N * NSTEPS;
    unsigned lin = (unsigned)ray * NSTEPS + (unsigned)s0;

    {   // positions: 12 consecutive floats at lin*3 (48B-aligned)
        float* pb = out + (size_t)lin * 3u;
        st4(pb + 0, P[0] * mf0, P[1]  * mf0, P[2]  * mf0, P[3]  * mf1);
        st4(pb + 4, P[4] * mf1, P[5]  * mf1, P[6]  * mf2, P[7]  * mf2);
        st4(pb + 8, P[8] * mf2, P[9]  * mf3, P[10] * mf3, P[11] * mf3);
    }

    {
        float t0 = fmaf((float)(s0 + 0), STEPF, tmin);
        float t1 = fmaf((float)(s0 + 1), STEPF, tmin);
        float t2 = fmaf((float)(s0 + 2), STEPF, tmin);
        float t3 = fmaf((float)(s0 + 3), STEPF, tmin);
        st4(out + (size_t)NS * 3u + lin, t0 * mf0, t1 * mf1, t2 * mf2, t3 * mf3);
        st4(out + (size_t)NS * 4u + lin, (t0 + STEPF) * mf0, (t1 + STEPF) * mf1,
                                         (t2 + STEPF) * mf2, (t3 + STEPF) * mf3);
    }

    float rf = (float)ray;
    st4(out + (size_t)NS * 5u + lin,
        (mbits & 1u) ? rf : -1.0f,
        (mbits & 2u) ? rf : -1.0f,
        (mbits & 4u) ? rf : -1.0f,
        (mbits & 8u) ? rf : -1.0f);

    st4(out + (size_t)NS * 6u + lin, mf0, mf1, mf2, mf3);
}

extern "C" void kernel_launch(void* const* d_in, const int* in_sizes, int n_in,
                              void* d_out, int out_size)
{
    const float* origins = (const float*)d_in[0];
    const float* dirs    = (const float*)d_in[1];
    const float* occs    = (const float*)d_in[2];
    const float* aabb    = (const float*)d_in[3];
    float* out           = (float*)d_out;

    int N = in_sizes[0] / 3;
    int total = N * (NSTEPS / 4);
    int block = 256;
    int grid = (total + block - 1) / block;
    nerfacc_sampler_kernel<<<grid, block>>>(origins, dirs, occs, aabb, out, N);
}

// round 11
// speedup vs baseline: 1.1612x; 1.0661x over previous
#include <cuda_runtime.h>
#include <math.h>
#include <stdint.h>

// NeRFAcc occupancy-grid sampler.
// Inputs: origins [N,3] f32, directions [N,3] f32, occs [128^3] f32, aabb [2,3] f32.
// Output (flat f32): positions [N,S,3] | t_starts [N,S] | t_ends [N,S] | ray_idx [N,S] | mask [N,S]

#define RESG 128
#define NSTEPS 320
#define STEPF 0.01f
// alpha = 1-exp(-occ*STEP) > 0.01  <=>  occ > -ln(0.99)/STEP = 1.00503358535...
#define OCC_THRE 1.0050335853f

__device__ __forceinline__ void stcs4(float* p, float a, float b, float c, float d) {
    float4 v = make_float4(a, b, c, d);
    __stcs(reinterpret_cast<float4*>(p), v);
}

__global__ __launch_bounds__(256, 8)
void nerfacc_sampler_kernel(const float* __restrict__ origins,
                            const float* __restrict__ dirs,
                            const float* __restrict__ occs,
                            const float* __restrict__ aabb,
                            float* __restrict__ out,
                            int N)
{
    const int CHUNKS = NSTEPS / 4;                 // 80 chunks of 4 steps
    int tid = blockIdx.x * blockDim.x + threadIdx.x;
    int total = N * CHUNKS;
    if (tid >= total) return;

    int ray = tid / CHUNKS;
    int s0  = (tid - ray * CHUNKS) * 4;

    // ---- per-ray data ----
    float ox = __ldg(origins + 3 * ray + 0);
    float oy = __ldg(origins + 3 * ray + 1);
    float oz = __ldg(origins + 3 * ray + 2);
    float dx = __ldg(dirs + 3 * ray + 0);
    float dy = __ldg(dirs + 3 * ray + 1);
    float dz = __ldg(dirs + 3 * ray + 2);

    float a0x = __ldg(aabb + 0), a0y = __ldg(aabb + 1), a0z = __ldg(aabb + 2);
    float a1x = __ldg(aabb + 3), a1y = __ldg(aabb + 4), a1z = __ldg(aabb + 5);

    // ---- robust slab intersection (matches reference exactly) ----
    float sdx = (fabsf(dx) < 1e-10f) ? 1e-10f : dx;
    float sdy = (fabsf(dy) < 1e-10f) ? 1e-10f : dy;
    float sdz = (fabsf(dz) < 1e-10f) ? 1e-10f : dz;
    float ivx = 1.0f / sdx, ivy = 1.0f / sdy, ivz = 1.0f / sdz;

    float t0x = (a0x - ox) * ivx, t1x = (a1x - ox) * ivx;
    float t0y = (a0y - oy) * ivy, t1y = (a1y - oy) * ivy;
    float t0z = (a0z - oz) * ivz, t1z = (a1z - oz) * ivz;

    float tmin = fmaxf(fmaxf(fminf(t0x, t1x), fminf(t0y, t1y)), fminf(t0z, t1z));
    float tmax = fminf(fminf(fmaxf(t0x, t1x), fmaxf(t0y, t1y)), fmaxf(t0z, t1z));
    tmin = fmaxf(tmin, 0.0f);                      // NEAR = 0

    float invsx = 1.0f / (a1x - a0x);
    float invsy = 1.0f / (a1y - a0y);
    float invsz = 1.0f / (a1z - a0z);

    bool ray_ok = (tmax > tmin);

    // ---- phase 1: positions + predicated gathers (4 loads in flight) ----
    float P[12];
    float occv[4];

    #pragma unroll
    for (int j = 0; j < 4; j++) {
        float t_start = fmaf((float)(s0 + j), STEPF, tmin);
        float t_end   = t_start + STEPF;
        float t_mid   = 0.5f * (t_start + t_end);

        float x = fmaf(dx, t_mid, ox);
        float y = fmaf(dy, t_mid, oy);
        float z = fmaf(dz, t_mid, oz);
        P[j * 3 + 0] = x;
        P[j * 3 + 1] = y;
        P[j * 3 + 2] = z;

        float ux = (x - a0x) * invsx;
        float uy = (y - a0y) * invsy;
        float uz = (z - a0z) * invsz;

        bool inside = (ux >= 0.0f) & (ux < 1.0f)
                    & (uy >= 0.0f) & (uy < 1.0f)
                    & (uz >= 0.0f) & (uz < 1.0f);

        occv[j] = 0.0f;   // occ=0 -> fails threshold -> mask 0
        if (inside && (t_end <= tmax) && ray_ok) {
            // inside => u in [0,1) => indices in [0,127], no clamp needed
            unsigned ix = (unsigned)(int)(ux * (float)RESG);
            unsigned iy = (unsigned)(int)(uy * (float)RESG);
            unsigned iz = (unsigned)(int)(uz * (float)RESG);
            occv[j] = __ldg(occs + ((((ix << 7) | iy) << 7) | iz));
        }
    }

    // ---- phase 2: threshold test (exact equivalent of alpha test, no expf) ----
    float mf0 = (occv[0] > OCC_THRE) ? 1.0f : 0.0f;
    float mf1 = (occv[1] > OCC_THRE) ? 1.0f : 0.0f;
    float mf2 = (occv[2] > OCC_THRE) ? 1.0f : 0.0f;
    float mf3 = (occv[3] > OCC_THRE) ? 1.0f : 0.0f;

    // ---- phase 3: streaming float4 stores ----
    unsigned NS  = (unsigned)N * NSTEPS;
    unsigned lin = (unsigned)ray * NSTEPS + (unsigned)s0;

    {   // positions: 12 consecutive floats at lin*3 (48B-aligned)
        float* pb = out + (size_t)lin * 3u;
        stcs4(pb + 0, P[0] * mf0, P[1]  * mf0, P[2]  * mf0, P[3]  * mf1);
        stcs4(pb + 4, P[4] * mf1, P[5]  * mf1, P[6]  * mf2, P[7]  * mf2);
        stcs4(pb + 8, P[8] * mf2, P[9]  * mf3, P[10] * mf3, P[11] * mf3);
    }

    {
        float t0 = fmaf((float)(s0 + 0), STEPF, tmin);
        float t1 = fmaf((float)(s0 + 1), STEPF, tmin);
        float t2 = fmaf((float)(s0 + 2), STEPF, tmin);
        float t3 = fmaf((float)(s0 + 3), STEPF, tmin);
        stcs4(out + (size_t)NS * 3u + lin, t0 * mf0, t1 * mf1, t2 * mf2, t3 * mf3);
        stcs4(out + (size_t)NS * 4u + lin, (t0 + STEPF) * mf0, (t1 + STEPF) * mf1,
                                           (t2 + STEPF) * mf2, (t3 + STEPF) * mf3);
    }

    float rf = (float)ray;
    stcs4(out + (size_t)NS * 5u + lin,
          mf0 != 0.0f ? rf : -1.0f,
          mf1 != 0.0f ? rf : -1.0f,
          mf2 != 0.0f ? rf : -1.0f,
          mf3 != 0.0f ? rf : -1.0f);

    stcs4(out + (size_t)NS * 6u + lin, mf0, mf1, mf2, mf3);
}

extern "C" void kernel_launch(void* const* d_in, const int* in_sizes, int n_in,
                              void* d_out, int out_size)
{
    const float* origins = (const float*)d_in[0];
    const float* dirs    = (const float*)d_in[1];
    const float* occs    = (const float*)d_in[2];
    const float* aabb    = (const float*)d_in[3];
    float* out           = (float*)d_out;

    int N = in_sizes[0] / 3;
    int total = N * (NSTEPS / 4);
    int block = 256;
    int grid = (total + block - 1) / block;
    nerfacc_sampler_kernel<<<grid, block>>>(origins, dirs, occs, aabb, out, N);
}

// round 12
// speedup vs baseline: 1.3149x; 1.1323x over previous
#include <cuda_runtime.h>
#include <math.h>
#include <stdint.h>

// NeRFAcc occupancy-grid sampler.
// Inputs: origins [N,3] f32, directions [N,3] f32, occs [128^3] f32, aabb [2,3] f32.
// Output (flat f32): positions [N,S,3] | t_starts [N,S] | t_ends [N,S] | ray_idx [N,S] | mask [N,S]

#define RESG 128
#define NSTEPS 320
#define STEPF 0.01f
// alpha = 1-exp(-occ*STEP) > 0.01  <=>  occ > -ln(0.99)/STEP = 1.00503358535...
#define OCC_THRE 1.0050335853f

// Blocked bit-grid: 128^3 bits = 256 KB. One 128B cache line covers an
// 8x4x32 (x,y,z) block of cells. Word layout within block: word = lx*4+ly,
// bit = lz (32 consecutive z-cells per word).
// word address = bx*4096 + by*128 + bz*32 + lx*4 + ly
__device__ uint32_t g_bitgrid[RESG * RESG * RESG / 32];

// ---- kernel 1: occs (8 MB) -> blocked bit grid (256 KB) ------------------
__global__ __launch_bounds__(256)
void build_bitgrid_kernel(const float* __restrict__ occs)
{
    unsigned tid = blockIdx.x * 256u + threadIdx.x;   // cell index, z fastest
    float v = __ldg(occs + tid);
    unsigned b = __ballot_sync(0xffffffffu, v > OCC_THRE);
    if ((threadIdx.x & 31u) == 0u) {
        unsigned ix = tid >> 14, iy = (tid >> 7) & 127u, iz = tid & 127u;
        unsigned addr = ((ix >> 3) << 12) | ((iy >> 2) << 7) | ((iz >> 5) << 5)
                      | ((ix & 7u) << 2) | (iy & 3u);
        g_bitgrid[addr] = b;
    }
}

// ---- kernel 2: sampler ----------------------------------------------------
// Warp = one 64-step window of one ray (320 steps = 5 warps/ray exactly).
// Lane L handles steps {seg*64+L, seg*64+32+L}: warp-gathers touch 32
// CONSECUTIVE samples -> few distinct bit-grid lines.
__global__ __launch_bounds__(256, 8)
void nerfacc_sampler_kernel(const float* __restrict__ origins,
                            const float* __restrict__ dirs,
                            const float* __restrict__ aabb,
                            float* __restrict__ out,
                            int N)
{
    unsigned tid  = blockIdx.x * 256u + threadIdx.x;
    unsigned warp = tid >> 5;
    unsigned lane = tid & 31u;
    unsigned ray  = warp / 5u;
    unsigned seg  = warp - ray * 5u;
    if ((int)ray >= N) return;

    // ---- per-ray data (warp-uniform broadcasts) ----
    float ox = __ldg(origins + 3 * ray + 0);
    float oy = __ldg(origins + 3 * ray + 1);
    float oz = __ldg(origins + 3 * ray + 2);
    float dx = __ldg(dirs + 3 * ray + 0);
    float dy = __ldg(dirs + 3 * ray + 1);
    float dz = __ldg(dirs + 3 * ray + 2);

    float a0x = __ldg(aabb + 0), a0y = __ldg(aabb + 1), a0z = __ldg(aabb + 2);
    float a1x = __ldg(aabb + 3), a1y = __ldg(aabb + 4), a1z = __ldg(aabb + 5);

    // ---- robust slab intersection (matches reference exactly) ----
    float sdx = (fabsf(dx) < 1e-10f) ? 1e-10f : dx;
    float sdy = (fabsf(dy) < 1e-10f) ? 1e-10f : dy;
    float sdz = (fabsf(dz) < 1e-10f) ? 1e-10f : dz;
    float ivx = 1.0f / sdx, ivy = 1.0f / sdy, ivz = 1.0f / sdz;

    float t0x = (a0x - ox) * ivx, t1x = (a1x - ox) * ivx;
    float t0y = (a0y - oy) * ivy, t1y = (a1y - oy) * ivy;
    float t0z = (a0z - oz) * ivz, t1z = (a1z - oz) * ivz;

    float tmin = fmaxf(fmaxf(fminf(t0x, t1x), fminf(t0y, t1y)), fminf(t0z, t1z));
    float tmax = fminf(fminf(fmaxf(t0x, t1x), fmaxf(t0y, t1y)), fmaxf(t0z, t1z));
    tmin = fmaxf(tmin, 0.0f);                      // NEAR = 0

    float invsx = 1.0f / (a1x - a0x);
    float invsy = 1.0f / (a1y - a0y);
    float invsz = 1.0f / (a1z - a0z);

    bool ray_ok = (tmax > tmin);

    int sA = (int)(seg * 64u + lane);              // steps: sA and sA+32

    float X[2], Y[2], Z[2];
    float T0[2];
    unsigned bit[2];

    // ---- phase 1: positions + predicated bit loads (both in flight) ----
    #pragma unroll
    for (int j = 0; j < 2; j++) {
        int s = sA + 32 * j;
        float t_start = fmaf((float)s, STEPF, tmin);
        float t_end   = t_start + STEPF;
        float t_mid   = 0.5f * (t_start + t_end);
        T0[j] = t_start;

        float x = fmaf(dx, t_mid, ox);
        float y = fmaf(dy, t_mid, oy);
        float z = fmaf(dz, t_mid, oz);
        X[j] = x; Y[j] = y; Z[j] = z;

        float ux = (x - a0x) * invsx;
        float uy = (y - a0y) * invsy;
        float uz = (z - a0z) * invsz;

        bool inside = (ux >= 0.0f) & (ux < 1.0f)
                    & (uy >= 0.0f) & (uy < 1.0f)
                    & (uz >= 0.0f) & (uz < 1.0f);

        bit[j] = 0u;
        if (inside && (t_end <= tmax) && ray_ok) {
            // inside => u in [0,1) => indices in [0,127]
            unsigned ix = (unsigned)(int)(ux * (float)RESG);
            unsigned iy = (unsigned)(int)(uy * (float)RESG);
            unsigned iz = (unsigned)(int)(uz * (float)RESG);
            unsigned addr = ((ix >> 3) << 12) | ((iy >> 2) << 7) | ((iz >> 5) << 5)
                          | ((ix & 7u) << 2) | (iy & 3u);
            uint32_t w = g_bitgrid[addr];
            bit[j] = (w >> (iz & 31u)) & 1u;
        }
    }

    // ---- phase 2: streaming scalar stores ----
    unsigned NS = (unsigned)N * NSTEPS;
    float rf = (float)ray;

    #pragma unroll
    for (int j = 0; j < 2; j++) {
        int s = sA + 32 * j;
        unsigned lin = ray * NSTEPS + (unsigned)s;
        float mf = bit[j] ? 1.0f : 0.0f;

        float* pb = out + (size_t)lin * 3u;
        __stcs(pb + 0, X[j] * mf);
        __stcs(pb + 1, Y[j] * mf);
        __stcs(pb + 2, Z[j] * mf);

        __stcs(out + (size_t)NS * 3u + lin, T0[j] * mf);
        __stcs(out + (size_t)NS * 4u + lin, (T0[j] + STEPF) * mf);
        __stcs(out + (size_t)NS * 5u + lin, bit[j] ? rf : -1.0f);
        __stcs(out + (size_t)NS * 6u + lin, mf);
    }
}

extern "C" void kernel_launch(void* const* d_in, const int* in_sizes, int n_in,
                              void* d_out, int out_size)
{
    const float* origins = (const float*)d_in[0];
    const float* dirs    = (const float*)d_in[1];
    const float* occs    = (const float*)d_in[2];
    const float* aabb    = (const float*)d_in[3];
    float* out           = (float*)d_out;

    int N = in_sizes[0] / 3;

    // kernel 1: occs -> blocked bit grid
    build_bitgrid_kernel<<<(RESG * RESG * RESG) / 256, 256>>>(occs);

    // kernel 2: sampler — 5 warps per ray, 2 steps per thread
    int total_threads = N * 5 * 32;
    int block = 256;
    int grid = (total_threads + block - 1) / block;
    nerfacc_sampler_kernel<<<grid, block>>>(origins, dirs, aabb, out, N);
}